// round 2
// baseline (speedup 1.0000x reference)
#include <cuda_runtime.h>
#include <math.h>

#define Bn 2
#define C 64
#define H 256
#define W 256
#define S (H*W)
#define HEADS 4
#define HD 16

typedef unsigned long long ull;

// Scratch (device globals -- no allocations allowed)
__device__ float g_conv[Bn*C*S];          // deform-conv output [B,C,S]
__device__ float g_G[Bn*HEADS*HD*HD];     // raw gram q.k
__device__ float g_qn2[Bn*HEADS*HD];      // sum q^2 per row
__device__ float g_kn2[Bn*HEADS*HD];      // sum k^2 per row

__device__ __forceinline__ void fma2(ull& d, ull a, ull b) {
    asm("fma.rn.f32x2 %0, %1, %2, %0;" : "+l"(d) : "l"(a), "l"(b));
}
__device__ __forceinline__ float2 unpack2(ull a) {
    float2 f; asm("mov.b64 {%0,%1}, %2;" : "=f"(f.x), "=f"(f.y) : "l"(a)); return f;
}

// ---------------------------------------------------------------------------
__global__ void zero_kernel() {
    int tid = threadIdx.x;
    for (int t = tid; t < Bn*HEADS*HD*HD; t += 256) g_G[t] = 0.f;
    for (int t = tid; t < Bn*HEADS*HD;    t += 256) { g_qn2[t] = 0.f; g_kn2[t] = 0.f; }
}

// ---------------------------------------------------------------------------
// Deformable 3x3 conv, f32x2 packed mainloop.
// Block = 128 pixels x 64 output channels, 128 threads.
// Thread tile: 8 px x 8 out-ch (64 f32x2 accumulators).
// Channel chunks of 4: s[4][9][128] (k-major), w pre-splatted float2 [4][9][64].
__global__ __launch_bounds__(128, 2) void deform_conv_kernel(
    const float* __restrict__ clone, const float* __restrict__ u,
    const float* __restrict__ v, const float* __restrict__ weight)
{
    __shared__ float  s_s[4][9][128];
    __shared__ float2 s_w[4][9][64];

    int tid   = threadIdx.x;
    int pix0  = blockIdx.x * 128;
    int b     = pix0 >> 16;
    int pbase = pix0 & (S-1);
    int tp = tid & 15;     // pixel group: pixels tp*8 .. tp*8+7
    int to = tid >> 4;     // out-ch group: o = to*8 .. to*8+7

    // Per-thread pixel params (pixel = pbase + tid), computed once.
    int p = pbase + tid;
    int y = p >> 8, x = p & 255;
    float py = (float)y + v[b*S + p];
    float px = (float)x + u[b*S + p];
    float fy = floorf(py), fx = floorf(px);
    int y0 = (int)fy, x0 = (int)fx;
    float wy = py - fy, wx = px - fx;

    int  rowoff[4];
    bool vy[4], vx[4];
    #pragma unroll
    for (int r = 0; r < 4; r++) {
        int yy = y0 - 1 + r;
        vy[r] = ((unsigned)yy < (unsigned)H);
        rowoff[r] = yy * W;
    }
    #pragma unroll
    for (int q = 0; q < 4; q++) {
        int xx = x0 - 1 + q;
        vx[q] = ((unsigned)xx < (unsigned)W);
    }

    ull acc[8][4];
    #pragma unroll
    for (int oo = 0; oo < 8; oo++)
        #pragma unroll
        for (int j = 0; j < 4; j++) acc[oo][j] = 0ull;

    for (int cb = 0; cb < C; cb += 4) {
        __syncthreads();   // protect smem reused from previous chunk
        // Stage splatted weights: [cl][k][o]
        for (int t = tid; t < 4*9*64; t += 128) {
            int cl  = t / 576;
            int rem = t - cl*576;
            int k   = rem >> 6;
            int o   = rem & 63;
            float wv_ = weight[(o*C + cb + cl)*9 + k];
            s_w[cl][k][o] = make_float2(wv_, wv_);
        }
        // Gather: this thread's pixel, 4 channels
        #pragma unroll
        for (int cl = 0; cl < 4; cl++) {
            const float* plane = clone + ((b*C + cb + cl) << 16);
            float patch[4][4];
            #pragma unroll
            for (int r = 0; r < 4; r++) {
                #pragma unroll
                for (int q = 0; q < 4; q++)
                    patch[r][q] = (vy[r] && vx[q]) ? __ldg(plane + rowoff[r] + (x0 - 1 + q)) : 0.f;
            }
            float hx[4][3];
            #pragma unroll
            for (int r = 0; r < 4; r++)
                #pragma unroll
                for (int kx = 0; kx < 3; kx++)
                    hx[r][kx] = patch[r][kx] + wx*(patch[r][kx+1] - patch[r][kx]);
            #pragma unroll
            for (int ky = 0; ky < 3; ky++)
                #pragma unroll
                for (int kx = 0; kx < 3; kx++)
                    s_s[cl][ky*3+kx][tid] = hx[ky][kx] + wy*(hx[ky+1][kx] - hx[ky][kx]);
        }
        __syncthreads();

        // Mainloop: packed f32x2 FMA
        #pragma unroll
        for (int cl = 0; cl < 4; cl++) {
            #pragma unroll
            for (int k = 0; k < 9; k++) {
                ulonglong2 sA = *(const ulonglong2*)&s_s[cl][k][tp*8];
                ulonglong2 sB = *(const ulonglong2*)&s_s[cl][k][tp*8 + 4];
                #pragma unroll
                for (int oo = 0; oo < 8; oo++) {
                    ull wsp = *(const ull*)&s_w[cl][k][to*8 + oo];
                    fma2(acc[oo][0], wsp, sA.x);
                    fma2(acc[oo][1], wsp, sA.y);
                    fma2(acc[oo][2], wsp, sB.x);
                    fma2(acc[oo][3], wsp, sB.y);
                }
            }
        }
    }

    // Epilogue: unpack + store
    #pragma unroll
    for (int oo = 0; oo < 8; oo++) {
        int o = to*8 + oo;
        float2 f0 = unpack2(acc[oo][0]);
        float2 f1 = unpack2(acc[oo][1]);
        float2 f2 = unpack2(acc[oo][2]);
        float2 f3 = unpack2(acc[oo][3]);
        float* dst = &g_conv[(b*C + o)*S + pbase + tp*8];
        *(float4*)dst       = make_float4(f0.x, f0.y, f1.x, f1.y);
        *(float4*)(dst + 4) = make_float4(f2.x, f2.y, f3.x, f3.y);
    }
}

// ---------------------------------------------------------------------------
// Gram + norms: per (b,h) compute G[16][16] = q_i . k_j over S, plus sum q^2,
// sum k^2 per row. Split S into 32 slices of 2048; atomic partial reduction.
__global__ __launch_bounds__(256) void dots_kernel(const float* __restrict__ xg) {
    __shared__ float qs[16][260];
    __shared__ float ks[16][260];
    __shared__ float s_nq[16], s_nk[16];

    int tid = threadIdx.x;
    int bh  = blockIdx.x >> 5;
    int sl  = blockIdx.x & 31;
    int b   = bh >> 2, hh = bh & 3;
    int i = tid >> 4, j = tid & 15;
    int s0 = sl * 2048;

    if (tid < 16) { s_nq[tid] = 0.f; s_nk[tid] = 0.f; }

    float g = 0.f, nqp = 0.f, nkp = 0.f;
    for (int ch = 0; ch < 8; ++ch) {
        __syncthreads();
        int sbase = s0 + ch*256;
        #pragma unroll
        for (int e = 0; e < 8; ++e) {
            int lin = tid + e*256;          // float4 unit, 0..2047
            int r = lin >> 6, c4 = lin & 63;
            const float* src = (r < 16)
                ? (xg     + (b*C + hh*HD + r)*S)
                : (g_conv + (b*C + hh*HD + (r-16))*S);
            float4 val = *(const float4*)(src + sbase + c4*4);
            float* dst = (r < 16) ? &qs[r][c4*4] : &ks[r-16][c4*4];
            dst[0] = val.x; dst[1] = val.y; dst[2] = val.z; dst[3] = val.w;
        }
        __syncthreads();
        #pragma unroll 8
        for (int s = 0; s < 256; s += 4) {
            float4 qv = *(const float4*)&qs[i][s];
            float4 kv = *(const float4*)&ks[j][s];
            g += qv.x*kv.x; g += qv.y*kv.y; g += qv.z*kv.z; g += qv.w*kv.w;
        }
        #pragma unroll 4
        for (int s = j; s < 256; s += 16) { float q0 = qs[i][s]; nqp += q0*q0; }
        #pragma unroll 4
        for (int s = i; s < 256; s += 16) { float k0 = ks[j][s]; nkp += k0*k0; }
    }
    atomicAdd(&g_G[bh*256 + i*16 + j], g);
    atomicAdd(&s_nq[i], nqp);
    atomicAdd(&s_nk[j], nkp);
    __syncthreads();
    if (tid < 16)       atomicAdd(&g_qn2[bh*16 + tid], s_nq[tid]);
    else if (tid < 32)  atomicAdd(&g_kn2[bh*16 + tid-16], s_nk[tid-16]);
}

// ---------------------------------------------------------------------------
// Fused softmax + out. Each block recomputes the 16x16 softmax for its (b,h)
// in smem (cheap), then out[c,s] = sum_d attn[c,d] * kv[d,s].
__global__ __launch_bounds__(256) void out_kernel(float* __restrict__ out,
                                                  const float* __restrict__ temp) {
    __shared__ float s_attn[16][16];
    int tid = threadIdx.x;
    int bh = blockIdx.x >> 5;      // 32 s-tiles of 2048
    int st = blockIdx.x & 31;
    int b = bh >> 2, hh = bh & 3;

    // softmax prologue: thread (i,j) handles one attn entry; row-reduce in half-warp
    {
        int i = tid >> 4, j = tid & 15;
        float dq = fmaxf(sqrtf(g_qn2[bh*16 + i]), 1e-12f);
        float dk = fmaxf(sqrtf(g_kn2[bh*16 + j]), 1e-12f);
        float T  = temp[hh];
        float l  = g_G[bh*256 + i*16 + j] / (dq*dk) * T;
        float m = l;
        #pragma unroll
        for (int off = 8; off > 0; off >>= 1)
            m = fmaxf(m, __shfl_xor_sync(0xffffffffu, m, off, 16));
        float e = expf(l - m);
        float ssum = e;
        #pragma unroll
        for (int off = 8; off > 0; off >>= 1)
            ssum += __shfl_xor_sync(0xffffffffu, ssum, off, 16);
        s_attn[i][j] = e / ssum;
    }
    __syncthreads();

    int ig = tid >> 6, scol = tid & 63;
    float a[4][16];
    #pragma unroll
    for (int ii = 0; ii < 4; ++ii)
        #pragma unroll
        for (int d = 0; d < 16; ++d)
            a[ii][d] = s_attn[ig*4+ii][d];

    int sbase0 = st * 2048;
    for (int sb = 0; sb < 32; ++sb) {
        int s = sbase0 + sb*64 + scol;
        float accv[4] = {0.f, 0.f, 0.f, 0.f};
        #pragma unroll
        for (int d = 0; d < 16; ++d) {
            float kvv = g_conv[(b*C + hh*HD + d)*S + s];
            #pragma unroll
            for (int ii = 0; ii < 4; ++ii) accv[ii] += a[ii][d]*kvv;
        }
        #pragma unroll
        for (int ii = 0; ii < 4; ++ii)
            out[(b*C + hh*HD + ig*4+ii)*S + s] = accv[ii];
    }
}

// ---------------------------------------------------------------------------
extern "C" void kernel_launch(void* const* d_in, const int* in_sizes, int n_in,
                              void* d_out, int out_size) {
    const float* clone  = (const float*)d_in[0];
    const float* xg     = (const float*)d_in[1];
    const float* u      = (const float*)d_in[2];
    const float* v      = (const float*)d_in[3];
    const float* weight = (const float*)d_in[4];
    const float* temp   = (const float*)d_in[5];
    float* out = (float*)d_out;

    zero_kernel<<<1, 256>>>();
    deform_conv_kernel<<<Bn*S/128, 128>>>(clone, u, v, weight);
    dots_kernel<<<Bn*HEADS*32, 256>>>(xg);
    out_kernel<<<Bn*HEADS*32, 256>>>(out, temp);
}